// round 2
// baseline (speedup 1.0000x reference)
#include <cuda_runtime.h>
#include <math.h>

#define NB 8
#define NC 256
#define HDIM 112
#define HW 12544
#define PLANE 3211264
#define PP 196
#define DD 16384
#define AA 3136
#define TGD 56
#define SPLITD 16
#define STATS_BLOCKS 64
#define STATS_CHUNK 50176

__device__ float g_xn[NB * PLANE];
__device__ float g_q [NB * PLANE];
__device__ float g_k [NB * PLANE];
__device__ float g_v [NB * PLANE];
__device__ float g_h [NB * PLANE];
__device__ float g_qp[NB * NC * AA];
__device__ float g_kp[NB * NC * AA];
__device__ float g_vp[NB * NC * AA];
__device__ float g_hg[NB * NC * AA];
__device__ float g_attp_part[NB * SPLITD * PP * PP];
__device__ float g_attp[NB * PP * PP];
__device__ float g_attg[(long)NB * AA * AA];
__device__ float g_psum[NB * STATS_BLOCKS];
__device__ float g_psq [NB * STATS_BLOCKS];
__device__ float g_mu  [NB];
__device__ float g_rstd[NB];

__global__ void stats_partial(const float* __restrict__ x) {
    const int b = blockIdx.y, blk = blockIdx.x, tid = threadIdx.x;
    const float* p = x + (long)b * PLANE + (long)blk * STATS_CHUNK;
    float s = 0.f, s2 = 0.f;
    for (int i = tid; i < STATS_CHUNK; i += 256) {
        float v = p[i];
        s += v; s2 += v * v;
    }
    __shared__ float ss[256], sq[256];
    ss[tid] = s; sq[tid] = s2; __syncthreads();
    for (int o = 128; o > 0; o >>= 1) {
        if (tid < o) { ss[tid] += ss[tid + o]; sq[tid] += sq[tid + o]; }
        __syncthreads();
    }
    if (tid == 0) {
        g_psum[b * STATS_BLOCKS + blk] = ss[0];
        g_psq [b * STATS_BLOCKS + blk] = sq[0];
    }
}

__global__ void stats_final() {
    int b = threadIdx.x;
    if (b >= NB) return;
    float s = 0.f, s2 = 0.f;
    for (int i = 0; i < STATS_BLOCKS; i++) {
        s  += g_psum[b * STATS_BLOCKS + i];
        s2 += g_psq [b * STATS_BLOCKS + i];
    }
    const float inv_n = 1.f / (float)PLANE;
    float mu  = s * inv_n;
    float var = s2 * inv_n - mu * mu;
    g_mu[b]   = mu;
    g_rstd[b] = rsqrtf(var + 1e-5f);
}

__global__ void groupnorm_k(const float* __restrict__ x,
                            const float* __restrict__ w,
                            const float* __restrict__ bta) {
    long t4 = (long)blockIdx.x * 256 + threadIdx.x;
    long idx = t4 * 4;
    int b = (int)(idx / PLANE);
    int c = (int)((idx / HW) % NC);
    float sc = g_rstd[b] * w[c];
    float sh = bta[c] - g_mu[b] * sc;
    float4 v = reinterpret_cast<const float4*>(x)[t4];
    float4 o;
    o.x = v.x * sc + sh; o.y = v.y * sc + sh;
    o.z = v.z * sc + sh; o.w = v.w * sc + sh;
    reinterpret_cast<float4*>(g_xn)[t4] = o;
}

// Fused Q/K/V GEMM: grid (196, 12, 8); y>>2 selects weight, y&3 the M tile.
__global__ __launch_bounds__(256)
void qkv_gemm(const float* __restrict__ xn,
              const float* __restrict__ wq, const float* __restrict__ bq,
              const float* __restrict__ wk, const float* __restrict__ bk,
              const float* __restrict__ wv, const float* __restrict__ bv,
              float* __restrict__ q, float* __restrict__ k,
              float* __restrict__ v) {
    const int TK = 16;
    __shared__ float As[TK][64 + 4];
    __shared__ float Bs[TK][64 + 4];

    const int wsel = blockIdx.y >> 2;
    const float* W    = wsel == 0 ? wq : (wsel == 1 ? wk : wv);
    const float* bias = wsel == 0 ? bq : (wsel == 1 ? bk : bv);
    float* out        = wsel == 0 ? q  : (wsel == 1 ? k  : v);

    const int m0 = (blockIdx.y & 3) * 64;
    const int n0 = blockIdx.x * 64;
    const int batch = blockIdx.z;
    const float* Bb = xn + (long)batch * PLANE;
    float* Cb = out + (long)batch * PLANE;

    const int tid = threadIdx.x;
    const int ty = tid >> 4, tx = tid & 15;
    float acc[4][4] = {};

    for (int kk = 0; kk < NC; kk += TK) {
        {
            int kl = tid & 15, mrow = tid >> 4;
            #pragma unroll
            for (int r = 0; r < 4; r++) {
                int mm = mrow + r * 16;
                As[kl][mm] = W[(long)(m0 + mm) * NC + (kk + kl)];
            }
        }
        {
            int n = tid & 63, kl = tid >> 6;
            #pragma unroll
            for (int r = 0; r < 4; r++) {
                int kq = kl + r * 4;
                Bs[kq][n] = Bb[(long)(kk + kq) * HW + (n0 + n)];
            }
        }
        __syncthreads();
        #pragma unroll
        for (int k2 = 0; k2 < TK; k2++) {
            const float4 a4 = *reinterpret_cast<const float4*>(&As[k2][ty * 4]);
            const float4 b4 = *reinterpret_cast<const float4*>(&Bs[k2][tx * 4]);
            const float ar[4] = {a4.x, a4.y, a4.z, a4.w};
            const float br[4] = {b4.x, b4.y, b4.z, b4.w};
            #pragma unroll
            for (int i = 0; i < 4; i++)
                #pragma unroll
                for (int j = 0; j < 4; j++)
                    acc[i][j] = fmaf(ar[i], br[j], acc[i][j]);
        }
        __syncthreads();
    }

    #pragma unroll
    for (int i = 0; i < 4; i++) {
        int m = m0 + ty * 4 + i;
        float bval = bias[m];
        #pragma unroll
        for (int j = 0; j < 4; j++) {
            int n = n0 + tx * 4 + j;
            Cb[(long)m * HW + n] = acc[i][j] + bval;
        }
    }
}

template<bool AT, bool BT>
__global__ __launch_bounds__(256)
void gemm64(const float* __restrict__ A, const float* __restrict__ Bm,
            float* __restrict__ C,
            int M, int N, int K,
            int lda, int ldb, int ldc,
            long strideA, long strideB, long strideC,
            int splitK, float alpha,
            const float* __restrict__ bias,
            const float* __restrict__ resid, long strideR) {
    const int TM = 64, TN = 64, TK = 16;
    __shared__ float As[TK][TM + 4];
    __shared__ float Bs[TK][TN + 4];

    const int z = blockIdx.z;
    const int batch = z / splitK;
    const int slice = z - batch * splitK;
    const int kChunk = (K + splitK - 1) / splitK;
    const int k0 = slice * kChunk;
    const int kEnd = min(K, k0 + kChunk);

    const float* Ab = A + (long)batch * strideA;
    const float* Bb = Bm + (long)batch * strideB;
    float* Cb = C + (long)z * strideC;

    const int m0 = blockIdx.y * TM;
    const int n0 = blockIdx.x * TN;
    const int tid = threadIdx.x;
    const int ty = tid >> 4, tx = tid & 15;

    float acc[4][4] = {};

    for (int kk = k0; kk < kEnd; kk += TK) {
        if (AT) {
            int m = tid & 63, kl = tid >> 6;
            #pragma unroll
            for (int r = 0; r < 4; r++) {
                int k = kl + r * 4;
                float v = 0.f;
                if (m0 + m < M && kk + k < kEnd)
                    v = Ab[(long)(kk + k) * lda + (m0 + m)];
                As[k][m] = v;
            }
        } else {
            int kl = tid & 15, mrow = tid >> 4;
            #pragma unroll
            for (int r = 0; r < 4; r++) {
                int mm = mrow + r * 16;
                float v = 0.f;
                if (m0 + mm < M && kk + kl < kEnd)
                    v = Ab[(long)(m0 + mm) * lda + (kk + kl)];
                As[kl][mm] = v;
            }
        }
        if (!BT) {
            int n = tid & 63, kl = tid >> 6;
            #pragma unroll
            for (int r = 0; r < 4; r++) {
                int k = kl + r * 4;
                float v = 0.f;
                if (n0 + n < N && kk + k < kEnd)
                    v = Bb[(long)(kk + k) * ldb + (n0 + n)];
                Bs[k][n] = v;
            }
        } else {
            int kl = tid & 15, nrow = tid >> 4;
            #pragma unroll
            for (int r = 0; r < 4; r++) {
                int nn = nrow + r * 16;
                float v = 0.f;
                if (n0 + nn < N && kk + kl < kEnd)
                    v = Bb[(long)(n0 + nn) * ldb + (kk + kl)];
                Bs[kl][nn] = v;
            }
        }
        __syncthreads();
        #pragma unroll
        for (int k = 0; k < TK; k++) {
            const float4 a4 = *reinterpret_cast<const float4*>(&As[k][ty * 4]);
            const float4 b4 = *reinterpret_cast<const float4*>(&Bs[k][tx * 4]);
            const float ar[4] = {a4.x, a4.y, a4.z, a4.w};
            const float br[4] = {b4.x, b4.y, b4.z, b4.w};
            #pragma unroll
            for (int i = 0; i < 4; i++)
                #pragma unroll
                for (int j = 0; j < 4; j++)
                    acc[i][j] = fmaf(ar[i], br[j], acc[i][j]);
        }
        __syncthreads();
    }

    #pragma unroll
    for (int i = 0; i < 4; i++) {
        int m = m0 + ty * 4 + i;
        if (m >= M) continue;
        float bval = bias ? bias[m] : 0.f;
        #pragma unroll
        for (int j = 0; j < 4; j++) {
            int n = n0 + tx * 4 + j;
            if (n >= N) continue;
            float vv = acc[i][j] * alpha + bval;
            if (resid)
                vv += resid[(long)batch * strideR + (long)m * ldc + n];
            Cb[(long)m * ldc + n] = vv;
        }
    }
}

__global__ void avgpool_k(const float* __restrict__ in, float* __restrict__ out) {
    int t = blockIdx.x * 256 + threadIdx.x;
    if (t >= NB * NC * AA) return;
    int p = t % AA;
    int bc = t / AA;
    int y = p / TGD, x = p % TGD;
    const float* src = in + (long)bc * HW + (long)(2 * y) * HDIM + 2 * x;
    out[t] = 0.25f * (src[0] + src[1] + src[HDIM] + src[HDIM + 1]);
}

__global__ void softmax_patch() {
    const int row = blockIdx.x;
    const int b = row / PP, p = row % PP;
    const int tid = threadIdx.x;
    float val = 0.f, v = -1e30f;
    if (tid < PP) {
        const float* base = g_attp_part + ((long)(b * SPLITD) * PP + p) * PP + tid;
        float s = 0.f;
        #pragma unroll
        for (int i = 0; i < SPLITD; i++) s += base[(long)i * PP * PP];
        val = s * 0.0078125f;
        v = val;
    }
    __shared__ float red[256];
    red[tid] = v; __syncthreads();
    for (int o = 128; o > 0; o >>= 1) {
        if (tid < o) red[tid] = fmaxf(red[tid], red[tid + o]);
        __syncthreads();
    }
    float m = red[0]; __syncthreads();
    float e = (tid < PP) ? expf(val - m) : 0.f;
    red[tid] = e; __syncthreads();
    for (int o = 128; o > 0; o >>= 1) {
        if (tid < o) red[tid] += red[tid + o];
        __syncthreads();
    }
    float inv = 1.f / red[0];
    if (tid < PP) g_attp[(long)row * PP + tid] = e * inv;
}

__global__ void softmax_glob() {
    const long row = blockIdx.x;
    float* base = g_attg + row * AA;
    const int tid = threadIdx.x;
    float vals[13];
    float m = -1e30f;
    #pragma unroll
    for (int i = 0; i < 13; i++) {
        int c = tid + i * 256;
        vals[i] = (c < AA) ? base[c] : -1e30f;
        m = fmaxf(m, vals[i]);
    }
    __shared__ float red[256];
    red[tid] = m; __syncthreads();
    for (int o = 128; o > 0; o >>= 1) {
        if (tid < o) red[tid] = fmaxf(red[tid], red[tid + o]);
        __syncthreads();
    }
    m = red[0]; __syncthreads();
    float s = 0.f;
    #pragma unroll
    for (int i = 0; i < 13; i++) {
        int c = tid + i * 256;
        float e = (c < AA) ? expf(vals[i] - m) : 0.f;
        vals[i] = e; s += e;
    }
    red[tid] = s; __syncthreads();
    for (int o = 128; o > 0; o >>= 1) {
        if (tid < o) red[tid] += red[tid + o];
        __syncthreads();
    }
    float inv = 1.f / red[0];
    #pragma unroll
    for (int i = 0; i < 13; i++) {
        int c = tid + i * 256;
        if (c < AA) base[c] = vals[i] * inv;
    }
}

__global__ void upsample_combine() {
    long t = (long)blockIdx.x * 256 + threadIdx.x;
    int x = (int)(t % HDIM);
    int y = (int)((t / HDIM) % HDIM);
    long bc = t / HW;
    float fy = y * 0.5f - 0.25f;
    float fx = x * 0.5f - 0.25f;
    int y0 = (int)floorf(fy), x0 = (int)floorf(fx);
    float wy = fy - (float)y0, wx = fx - (float)x0;
    int y0c = max(y0, 0), y1c = min(y0 + 1, TGD - 1);
    int x0c = max(x0, 0), x1c = min(x0 + 1, TGD - 1);
    const float* src = g_hg + bc * AA;
    float v00 = src[y0c * TGD + x0c], v01 = src[y0c * TGD + x1c];
    float v10 = src[y1c * TGD + x0c], v11 = src[y1c * TGD + x1c];
    float up = (1.f - wy) * ((1.f - wx) * v00 + wx * v01)
             +        wy  * ((1.f - wx) * v10 + wx * v11);
    g_h[t] += 0.25f * up;
}

extern "C" void kernel_launch(void* const* d_in, const int* in_sizes, int n_in,
                              void* d_out, int out_size) {
    (void)in_sizes; (void)n_in; (void)out_size;
    const float* x     = (const float*)d_in[0];
    const float* gn_w  = (const float*)d_in[1];
    const float* gn_b  = (const float*)d_in[2];
    const float* wq    = (const float*)d_in[3];
    const float* bq    = (const float*)d_in[4];
    const float* wk    = (const float*)d_in[5];
    const float* bk    = (const float*)d_in[6];
    const float* wv    = (const float*)d_in[7];
    const float* bv    = (const float*)d_in[8];
    const float* wproj = (const float*)d_in[9];
    float* out = (float*)d_out;

    float *xn, *q, *k, *v, *h, *qp, *kp, *vp, *hg, *attp_part, *attp, *attg;
    cudaGetSymbolAddress((void**)&xn, g_xn);
    cudaGetSymbolAddress((void**)&q,  g_q);
    cudaGetSymbolAddress((void**)&k,  g_k);
    cudaGetSymbolAddress((void**)&v,  g_v);
    cudaGetSymbolAddress((void**)&h,  g_h);
    cudaGetSymbolAddress((void**)&qp, g_qp);
    cudaGetSymbolAddress((void**)&kp, g_kp);
    cudaGetSymbolAddress((void**)&vp, g_vp);
    cudaGetSymbolAddress((void**)&hg, g_hg);
    cudaGetSymbolAddress((void**)&attp_part, g_attp_part);
    cudaGetSymbolAddress((void**)&attp, g_attp);
    cudaGetSymbolAddress((void**)&attg, g_attg);

    stats_partial<<<dim3(STATS_BLOCKS, NB), 256>>>(x);
    stats_final<<<1, 32>>>();
    groupnorm_k<<<25088, 256>>>(x, gn_w, gn_b);

    qkv_gemm<<<dim3(HW / 64, 12, NB), 256>>>(xn, wq, bq, wk, bk, wv, bv, q, k, v);

    avgpool_k<<<25088, 256>>>(q, qp);
    avgpool_k<<<25088, 256>>>(k, kp);
    avgpool_k<<<25088, 256>>>(v, vp);

    dim3 gpatt(4, 4, NB * SPLITD);
    gemm64<true,false><<<gpatt, 256>>>(q, k, attp_part, PP, PP, DD, PP, PP, PP,
                                       PLANE, PLANE, (long)PP * PP,
                                       SPLITD, 1.f, nullptr, nullptr, 0);
    softmax_patch<<<NB * PP, 256>>>();

    dim3 ghp(4, DD / 64, NB);
    gemm64<false,true><<<ghp, 256>>>(v, attp, h, DD, PP, PP, PP, PP, PP,
                                     PLANE, (long)PP * PP, PLANE,
                                     1, 0.75f, nullptr, nullptr, 0);

    dim3 gag(AA / 64, AA / 64, NB);
    gemm64<true,false><<<gag, 256>>>(qp, kp, attg, AA, AA, NC, AA, AA, AA,
                                     (long)NC * AA, (long)NC * AA, (long)AA * AA,
                                     1, 0.0625f, nullptr, nullptr, 0);
    softmax_glob<<<NB * AA, 256>>>();

    dim3 ghg(AA / 64, NC / 64, NB);
    gemm64<false,true><<<ghg, 256>>>(vp, attg, hg, NC, AA, AA, AA, AA, AA,
                                     (long)NC * AA, (long)AA * AA, (long)NC * AA,
                                     1, 1.f, nullptr, nullptr, 0);

    upsample_combine<<<100352, 256>>>();

    dim3 gproj(HW / 64, NC / 64, NB);
    gemm64<false,false><<<gproj, 256>>>(wproj, h, out, NC, HW, NC, NC, HW, HW,
                                        0, PLANE, PLANE, 1, 1.f, nullptr, x, PLANE);
}

// round 5
// speedup vs baseline: 2.0210x; 2.0210x over previous
#include <cuda_runtime.h>
#include <cuda_bf16.h>
#include <stdint.h>
#include <math.h>

#define NB 8
#define NC 256
#define HDIM 112
#define HW 12544
#define PLANE 3211264
#define PP 196
#define DD 16384
#define AA 3136
#define TGD 56
#define SPLITD 16
#define STATS_BLOCKS 64
#define STATS_CHUNK 50176

__device__ float g_xn[NB * PLANE];
__device__ float g_q [NB * PLANE];
__device__ float g_k [NB * PLANE];
__device__ float g_v [NB * PLANE];
__device__ float g_h [NB * PLANE];
__device__ float g_qp[NB * NC * AA];
__device__ float g_kp[NB * NC * AA];
__device__ float g_vp[NB * NC * AA];
__device__ float g_hg[NB * NC * AA];
__device__ float g_attp_part[NB * SPLITD * PP * PP];
__device__ float g_attp[NB * PP * PP];
__device__ float g_attg[(long)NB * AA * AA];
__device__ float g_psum[NB * STATS_BLOCKS];
__device__ float g_psq [NB * STATS_BLOCKS];
__device__ float g_mu  [NB];
__device__ float g_rstd[NB];

// ---------------------------------------------------------------------------
// GroupNorm (two-stage deterministic reduction)
// ---------------------------------------------------------------------------
__global__ void stats_partial(const float* __restrict__ x) {
    const int b = blockIdx.y, blk = blockIdx.x, tid = threadIdx.x;
    const float* p = x + (long)b * PLANE + (long)blk * STATS_CHUNK;
    float s = 0.f, s2 = 0.f;
    for (int i = tid; i < STATS_CHUNK; i += 256) {
        float v = p[i];
        s += v; s2 += v * v;
    }
    __shared__ float ss[256], sq[256];
    ss[tid] = s; sq[tid] = s2; __syncthreads();
    for (int o = 128; o > 0; o >>= 1) {
        if (tid < o) { ss[tid] += ss[tid + o]; sq[tid] += sq[tid + o]; }
        __syncthreads();
    }
    if (tid == 0) {
        g_psum[b * STATS_BLOCKS + blk] = ss[0];
        g_psq [b * STATS_BLOCKS + blk] = sq[0];
    }
}

__global__ void stats_final() {
    int b = threadIdx.x;
    if (b >= NB) return;
    float s = 0.f, s2 = 0.f;
    for (int i = 0; i < STATS_BLOCKS; i++) {
        s  += g_psum[b * STATS_BLOCKS + i];
        s2 += g_psq [b * STATS_BLOCKS + i];
    }
    const float inv_n = 1.f / (float)PLANE;
    float mu  = s * inv_n;
    float var = s2 * inv_n - mu * mu;
    g_mu[b]   = mu;
    g_rstd[b] = rsqrtf(var + 1e-5f);
}

__global__ void groupnorm_k(const float* __restrict__ x,
                            const float* __restrict__ w,
                            const float* __restrict__ bta) {
    long t4 = (long)blockIdx.x * 256 + threadIdx.x;
    long idx = t4 * 4;
    int b = (int)(idx / PLANE);
    int c = (int)((idx / HW) % NC);
    float sc = g_rstd[b] * w[c];
    float sh = bta[c] - g_mu[b] * sc;
    float4 v = reinterpret_cast<const float4*>(x)[t4];
    float4 o;
    o.x = v.x * sc + sh; o.y = v.y * sc + sh;
    o.z = v.z * sc + sh; o.w = v.w * sc + sh;
    reinterpret_cast<float4*>(g_xn)[t4] = o;
}

// ---------------------------------------------------------------------------
// bf16 tensor-core GEMM (mma.sync m16n8k16, fp32 accumulate).
// Block tile 64x64x16, 128 threads = 4 warps, warp tile 32x32.
// Smem K-contiguous: As[m][k], Bs[n][k], stride SKB=24 (conflict-free frags).
// ---------------------------------------------------------------------------
__device__ __forceinline__ void mma_bf16(float* c,
                                         const uint32_t* a,
                                         uint32_t b0, uint32_t b1) {
    asm volatile(
        "mma.sync.aligned.m16n8k16.row.col.f32.bf16.bf16.f32 "
        "{%0,%1,%2,%3}, {%4,%5,%6,%7}, {%8,%9}, {%0,%1,%2,%3};\n"
        : "+f"(c[0]), "+f"(c[1]), "+f"(c[2]), "+f"(c[3])
        : "r"(a[0]), "r"(a[1]), "r"(a[2]), "r"(a[3]), "r"(b0), "r"(b1));
}

#define SKB 24   // smem k stride (bf16 elems)

template<bool AT, bool BT>
__global__ __launch_bounds__(128)
void gemm_mma(const float* __restrict__ A, const float* __restrict__ Bm,
              float* __restrict__ C,
              int M, int N, int K,
              int lda, int ldb, int ldc,
              long strideA, long strideB, long strideC,
              int splitK, float alpha,
              const float* __restrict__ bias,
              const float* __restrict__ resid, long strideR) {
    __shared__ __nv_bfloat16 As[64][SKB];
    __shared__ __nv_bfloat16 Bs[64][SKB];

    const int z = blockIdx.z;
    const int batch = z / splitK;
    const int slice = z - batch * splitK;
    const int kChunk = (K + splitK - 1) / splitK;
    const int k0 = slice * kChunk;
    const int kEnd = min(K, k0 + kChunk);

    const float* Ab = A + (long)batch * strideA;
    const float* Bb = Bm + (long)batch * strideB;
    float* Cb = C + (long)z * strideC;

    const int m0 = blockIdx.y * 64;
    const int n0 = blockIdx.x * 64;
    const int tid = threadIdx.x;
    const int lane = tid & 31, warp = tid >> 5;
    const int wm = (warp >> 1) * 32, wn = (warp & 1) * 32;
    const int g = lane >> 2, t = lane & 3;

    float acc[2][4][4] = {};

    for (int kk = k0; kk < kEnd; kk += 16) {
        // ---- stage A -> As[m][k] ----
        if (AT) {
            #pragma unroll
            for (int r = 0; r < 8; r++) {
                int task = tid + r * 128;
                int m = task & 63, kq = task >> 6;
                float v = 0.f;
                if (m0 + m < M && kk + kq < kEnd)
                    v = Ab[(long)(kk + kq) * lda + (m0 + m)];
                As[m][kq] = __float2bfloat16(v);
            }
        } else {
            #pragma unroll
            for (int r = 0; r < 8; r++) {
                int task = tid + r * 128;
                int m = task >> 4, kq = task & 15;
                float v = 0.f;
                if (m0 + m < M && kk + kq < kEnd)
                    v = Ab[(long)(m0 + m) * lda + (kk + kq)];
                As[m][kq] = __float2bfloat16(v);
            }
        }
        // ---- stage B -> Bs[n][k] ----
        if (!BT) {
            #pragma unroll
            for (int r = 0; r < 8; r++) {
                int task = tid + r * 128;
                int n = task & 63, kq = task >> 6;
                float v = 0.f;
                if (n0 + n < N && kk + kq < kEnd)
                    v = Bb[(long)(kk + kq) * ldb + (n0 + n)];
                Bs[n][kq] = __float2bfloat16(v);
            }
        } else {
            #pragma unroll
            for (int r = 0; r < 8; r++) {
                int task = tid + r * 128;
                int n = task >> 4, kq = task & 15;
                float v = 0.f;
                if (n0 + n < N && kk + kq < kEnd)
                    v = Bb[(long)(n0 + n) * ldb + (kk + kq)];
                Bs[n][kq] = __float2bfloat16(v);
            }
        }
        __syncthreads();

        uint32_t af[2][4];
        #pragma unroll
        for (int i = 0; i < 2; i++) {
            int r = wm + i * 16 + g;
            af[i][0] = *reinterpret_cast<const uint32_t*>(&As[r][2 * t]);
            af[i][1] = *reinterpret_cast<const uint32_t*>(&As[r + 8][2 * t]);
            af[i][2] = *reinterpret_cast<const uint32_t*>(&As[r][2 * t + 8]);
            af[i][3] = *reinterpret_cast<const uint32_t*>(&As[r + 8][2 * t + 8]);
        }
        #pragma unroll
        for (int j = 0; j < 4; j++) {
            int c = wn + j * 8 + g;
            uint32_t b0 = *reinterpret_cast<const uint32_t*>(&Bs[c][2 * t]);
            uint32_t b1 = *reinterpret_cast<const uint32_t*>(&Bs[c][2 * t + 8]);
            mma_bf16(acc[0][j], af[0], b0, b1);
            mma_bf16(acc[1][j], af[1], b0, b1);
        }
        __syncthreads();
    }

    #pragma unroll
    for (int i = 0; i < 2; i++) {
        int r0 = m0 + wm + i * 16 + g;
        int r1 = r0 + 8;
        #pragma unroll
        for (int j = 0; j < 4; j++) {
            int c0 = n0 + wn + j * 8 + 2 * t;
            int c1 = c0 + 1;
            #pragma unroll
            for (int e = 0; e < 4; e++) {
                int m = (e < 2) ? r0 : r1;
                int n = (e & 1) ? c1 : c0;
                if (m >= M || n >= N) continue;
                float vv = acc[i][j][e] * alpha;
                if (bias)  vv += bias[m];
                if (resid) vv += resid[(long)batch * strideR + (long)m * ldc + n];
                Cb[(long)m * ldc + n] = vv;
            }
        }
    }
}

// ---------------------------------------------------------------------------
// Fused Q/K/V mma GEMM: grid (196, 12, 8); y>>2 selects weight, y&3 M-tile.
// Dims exact (M=256,N=12544,K=256): no bounds checks. L2 reuse of xn strips.
// ---------------------------------------------------------------------------
__global__ __launch_bounds__(128)
void qkv_mma(const float* __restrict__ xn,
             const float* __restrict__ wq, const float* __restrict__ bq,
             const float* __restrict__ wk, const float* __restrict__ bk,
             const float* __restrict__ wv, const float* __restrict__ bv,
             float* __restrict__ q, float* __restrict__ k,
             float* __restrict__ v) {
    __shared__ __nv_bfloat16 As[64][SKB];
    __shared__ __nv_bfloat16 Bs[64][SKB];

    const int wsel = blockIdx.y >> 2;
    const float* W    = wsel == 0 ? wq : (wsel == 1 ? wk : wv);
    const float* bias = wsel == 0 ? bq : (wsel == 1 ? bk : bv);
    float* outp       = wsel == 0 ? q  : (wsel == 1 ? k  : v);

    const int m0 = (blockIdx.y & 3) * 64;
    const int n0 = blockIdx.x * 64;
    const int batch = blockIdx.z;
    const float* Bb = xn + (long)batch * PLANE;
    float* Cb = outp + (long)batch * PLANE;

    const int tid = threadIdx.x;
    const int lane = tid & 31, warp = tid >> 5;
    const int wm = (warp >> 1) * 32, wn = (warp & 1) * 32;
    const int g = lane >> 2, t = lane & 3;

    float acc[2][4][4] = {};

    for (int kk = 0; kk < NC; kk += 16) {
        #pragma unroll
        for (int r = 0; r < 8; r++) {
            int task = tid + r * 128;
            int m = task >> 4, kq = task & 15;
            As[m][kq] = __float2bfloat16(W[(long)(m0 + m) * NC + (kk + kq)]);
        }
        #pragma unroll
        for (int r = 0; r < 8; r++) {
            int task = tid + r * 128;
            int n = task & 63, kq = task >> 6;
            Bs[n][kq] = __float2bfloat16(Bb[(long)(kk + kq) * HW + (n0 + n)]);
        }
        __syncthreads();

        uint32_t af[2][4];
        #pragma unroll
        for (int i = 0; i < 2; i++) {
            int r = wm + i * 16 + g;
            af[i][0] = *reinterpret_cast<const uint32_t*>(&As[r][2 * t]);
            af[i][1] = *reinterpret_cast<const uint32_t*>(&As[r + 8][2 * t]);
            af[i][2] = *reinterpret_cast<const uint32_t*>(&As[r][2 * t + 8]);
            af[i][3] = *reinterpret_cast<const uint32_t*>(&As[r + 8][2 * t + 8]);
        }
        #pragma unroll
        for (int j = 0; j < 4; j++) {
            int c = wn + j * 8 + g;
            uint32_t b0 = *reinterpret_cast<const uint32_t*>(&Bs[c][2 * t]);
            uint32_t b1 = *reinterpret_cast<const uint32_t*>(&Bs[c][2 * t + 8]);
            mma_bf16(acc[0][j], af[0], b0, b1);
            mma_bf16(acc[1][j], af[1], b0, b1);
        }
        __syncthreads();
    }

    #pragma unroll
    for (int i = 0; i < 2; i++) {
        int r0 = m0 + wm + i * 16 + g;
        int r1 = r0 + 8;
        #pragma unroll
        for (int j = 0; j < 4; j++) {
            int c0 = n0 + wn + j * 8 + 2 * t;
            #pragma unroll
            for (int e = 0; e < 4; e++) {
                int m = (e < 2) ? r0 : r1;
                int n = (e & 1) ? c0 + 1 : c0;
                Cb[(long)m * HW + n] = acc[i][j][e] + bias[m];
            }
        }
    }
}

// ---------------------------------------------------------------------------
// 2x2 average pool 112->56
// ---------------------------------------------------------------------------
__global__ void avgpool_k(const float* __restrict__ in, float* __restrict__ out) {
    int t = blockIdx.x * 256 + threadIdx.x;
    if (t >= NB * NC * AA) return;
    int p = t % AA;
    int bc = t / AA;
    int y = p / TGD, x = p % TGD;
    const float* src = in + (long)bc * HW + (long)(2 * y) * HDIM + 2 * x;
    out[t] = 0.25f * (src[0] + src[1] + src[HDIM] + src[HDIM + 1]);
}

// ---------------------------------------------------------------------------
// Patch softmax: reduce SPLITD partials, scale 1/128, softmax over 196
// ---------------------------------------------------------------------------
__global__ void softmax_patch() {
    const int row = blockIdx.x;
    const int b = row / PP, p = row % PP;
    const int tid = threadIdx.x;
    float val = 0.f, v = -1e30f;
    if (tid < PP) {
        const float* base = g_attp_part + ((long)(b * SPLITD) * PP + p) * PP + tid;
        float s = 0.f;
        #pragma unroll
        for (int i = 0; i < SPLITD; i++) s += base[(long)i * PP * PP];
        val = s * 0.0078125f;
        v = val;
    }
    __shared__ float red[256];
    red[tid] = v; __syncthreads();
    for (int o = 128; o > 0; o >>= 1) {
        if (tid < o) red[tid] = fmaxf(red[tid], red[tid + o]);
        __syncthreads();
    }
    float m = red[0]; __syncthreads();
    float e = (tid < PP) ? expf(val - m) : 0.f;
    red[tid] = e; __syncthreads();
    for (int o = 128; o > 0; o >>= 1) {
        if (tid < o) red[tid] += red[tid + o];
        __syncthreads();
    }
    float inv = 1.f / red[0];
    if (tid < PP) g_attp[(long)row * PP + tid] = e * inv;
}

// ---------------------------------------------------------------------------
// Global softmax: in-place rows of 3136, register-resident
// ---------------------------------------------------------------------------
__global__ void softmax_glob() {
    const long row = blockIdx.x;
    float* base = g_attg + row * AA;
    const int tid = threadIdx.x;
    float vals[13];
    float m = -1e30f;
    #pragma unroll
    for (int i = 0; i < 13; i++) {
        int c = tid + i * 256;
        vals[i] = (c < AA) ? base[c] : -1e30f;
        m = fmaxf(m, vals[i]);
    }
    __shared__ float red[256];
    red[tid] = m; __syncthreads();
    for (int o = 128; o > 0; o >>= 1) {
        if (tid < o) red[tid] = fmaxf(red[tid], red[tid + o]);
        __syncthreads();
    }
    m = red[0]; __syncthreads();
    float s = 0.f;
    #pragma unroll
    for (int i = 0; i < 13; i++) {
        int c = tid + i * 256;
        float e = (c < AA) ? expf(vals[i] - m) : 0.f;
        vals[i] = e; s += e;
    }
    red[tid] = s; __syncthreads();
    for (int o = 128; o > 0; o >>= 1) {
        if (tid < o) red[tid] += red[tid + o];
        __syncthreads();
    }
    float inv = 1.f / red[0];
    #pragma unroll
    for (int i = 0; i < 13; i++) {
        int c = tid + i * 256;
        if (c < AA) base[c] = vals[i] * inv;
    }
}

// ---------------------------------------------------------------------------
// Bilinear upsample 56->112 + combine: g_h += 0.25 * up(g_hg)
// ---------------------------------------------------------------------------
__global__ void upsample_combine() {
    long t = (long)blockIdx.x * 256 + threadIdx.x;
    int x = (int)(t % HDIM);
    int y = (int)((t / HDIM) % HDIM);
    long bc = t / HW;
    float fy = y * 0.5f - 0.25f;
    float fx = x * 0.5f - 0.25f;
    int y0 = (int)floorf(fy), x0 = (int)floorf(fx);
    float wy = fy - (float)y0, wx = fx - (float)x0;
    int y0c = max(y0, 0), y1c = min(y0 + 1, TGD - 1);
    int x0c = max(x0, 0), x1c = min(x0 + 1, TGD - 1);
    const float* src = g_hg + bc * AA;
    float v00 = src[y0c * TGD + x0c], v01 = src[y0c * TGD + x1c];
    float v10 = src[y1c * TGD + x0c], v11 = src[y1c * TGD + x1c];
    float up = (1.f - wy) * ((1.f - wx) * v00 + wx * v01)
             +        wy  * ((1.f - wx) * v10 + wx * v11);
    g_h[t] += 0.25f * up;
}

// ---------------------------------------------------------------------------
// Launch
// ---------------------------------------------------------------------------
extern "C" void kernel_launch(void* const* d_in, const int* in_sizes, int n_in,
                              void* d_out, int out_size) {
    (void)in_sizes; (void)n_in; (void)out_size;
    const float* x     = (const float*)d_in[0];
    const float* gn_w  = (const float*)d_in[1];
    const float* gn_b  = (const float*)d_in[2];
    const float* wq    = (const float*)d_in[3];
    const float* bq    = (const float*)d_in[4];
    const float* wk    = (const float*)d_in[5];
    const float* bk    = (const float*)d_in[6];
    const float* wv    = (const float*)d_in[7];
    const float* bv    = (const float*)d_in[8];
    const float* wproj = (const float*)d_in[9];
    float* out = (float*)d_out;

    float *xn, *q, *k, *v, *h, *qp, *kp, *vp, *hg, *attp_part, *attp, *attg;
    cudaGetSymbolAddress((void**)&xn, g_xn);
    cudaGetSymbolAddress((void**)&q,  g_q);
    cudaGetSymbolAddress((void**)&k,  g_k);
    cudaGetSymbolAddress((void**)&v,  g_v);
    cudaGetSymbolAddress((void**)&h,  g_h);
    cudaGetSymbolAddress((void**)&qp, g_qp);
    cudaGetSymbolAddress((void**)&kp, g_kp);
    cudaGetSymbolAddress((void**)&vp, g_vp);
    cudaGetSymbolAddress((void**)&hg, g_hg);
    cudaGetSymbolAddress((void**)&attp_part, g_attp_part);
    cudaGetSymbolAddress((void**)&attp, g_attp);
    cudaGetSymbolAddress((void**)&attg, g_attg);

    // 1. GroupNorm
    stats_partial<<<dim3(STATS_BLOCKS, NB), 256>>>(x);
    stats_final<<<1, 32>>>();
    groupnorm_k<<<25088, 256>>>(x, gn_w, gn_b);

    // 2. Fused Q/K/V 1x1 convs on tensor cores
    qkv_mma<<<dim3(HW / 64, 12, NB), 128>>>(xn, wq, bq, wk, bk, wv, bv, q, k, v);

    // 3. 2x2 avg pool
    avgpool_k<<<25088, 256>>>(q, qp);
    avgpool_k<<<25088, 256>>>(k, kp);
    avgpool_k<<<25088, 256>>>(v, vp);

    // 4. Patch attention logits (split-K=16, deterministic partials)
    dim3 gpatt(4, 4, NB * SPLITD);
    gemm_mma<true,false><<<gpatt, 128>>>(q, k, attp_part, PP, PP, DD, PP, PP, PP,
                                         PLANE, PLANE, (long)PP * PP,
                                         SPLITD, 1.f, nullptr, nullptr, 0);
    softmax_patch<<<NB * PP, 256>>>();

    // 5. h_patch = 0.75 * V @ att^T
    dim3 ghp(4, DD / 64, NB);
    gemm_mma<false,true><<<ghp, 128>>>(v, attp, h, DD, PP, PP, PP, PP, PP,
                                       PLANE, (long)PP * PP, PLANE,
                                       1, 0.75f, nullptr, nullptr, 0);

    // 6. Global attention logits (3136x3136, K=256)
    dim3 gag(AA / 64, AA / 64, NB);
    gemm_mma<true,false><<<gag, 128>>>(qp, kp, attg, AA, AA, NC, AA, AA, AA,
                                       (long)NC * AA, (long)NC * AA, (long)AA * AA,
                                       1, 0.0625f, nullptr, nullptr, 0);
    softmax_glob<<<NB * AA, 256>>>();

    // 7. h_glob = Vp @ att_g^T
    dim3 ghg(AA / 64, NC / 64, NB);
    gemm_mma<false,true><<<ghg, 128>>>(vp, attg, hg, NC, AA, AA, AA, AA, AA,
                                       (long)NC * AA, (long)AA * AA, (long)NC * AA,
                                       1, 1.f, nullptr, nullptr, 0);

    // 8. Upsample + combine
    upsample_combine<<<100352, 256>>>();

    // 9. out = x + W_proj @ h
    dim3 gproj(HW / 64, NC / 64, NB);
    gemm_mma<false,false><<<gproj, 128>>>(wproj, h, out, NC, HW, NC, NC, HW, HW,
                                          0, PLANE, PLANE, 1, 1.f, nullptr, x, PLANE);
}